// round 10
// baseline (speedup 1.0000x reference)
#include <cuda_runtime.h>
#include <cstdint>

#define N_NODES 50000
#define F_DIM 512
#define C_DIM 64
#define O_DIM 256
#define GRID_MAX 152
#define NT 64
#define NTILES ((N_NODES + NT - 1) / NT)   // 782
#define THREADS 512
#define WPT_STRIDE 516                     // padded row (floats) -> conflict-free column reads

typedef unsigned long long ull;

// smem float offsets
#define OFF_WPT 0                          // WpT [64 c][516] fp32 (132096 B)
#define OFF_XB  33024                      // 16 warps x 1024 floats (4KB private each)
#define OFF_S   49408                      // s [64 n][64 c] fp32 (16KB)
#define OFF_BP  53504                      // 64 floats
#define OFF_CS  53568                      // 64 floats
#define SMEM_FLOATS 53632                  // 214528 B

// Scratch (static device arrays; no allocation)
__device__ float g_Mpart[GRID_MAX * C_DIM * F_DIM];
__device__ float g_cspart[GRID_MAX * C_DIM];
__device__ float g_M[C_DIM * F_DIM];
__device__ float g_cs[C_DIM];
__device__ float g_pooled[C_DIM * F_DIM];
__device__ unsigned g_bar;                 // monotonic grid barrier counter

static __device__ __forceinline__ ull pack2(float lo, float hi) {
    ull r; asm("mov.b64 %0, {%1,%2};" : "=l"(r) : "f"(lo), "f"(hi)); return r;
}
static __device__ __forceinline__ void unpack2(ull v, float& lo, float& hi) {
    asm("mov.b64 {%0,%1}, %2;" : "=f"(lo), "=f"(hi) : "l"(v));
}
static __device__ __forceinline__ ull fma2(ull a, ull b, ull c) {
    ull d; asm("fma.rn.f32x2 %0, %1, %2, %3;" : "=l"(d) : "l"(a), "l"(b), "l"(c)); return d;
}

// Grid-wide barrier: all CTAs resident (grid == #SMs, occ 1). Monotonic counter.
static __device__ __forceinline__ void grid_sync() {
    __syncthreads();
    __threadfence();
    if (threadIdx.x == 0) {
        unsigned old = atomicAdd(&g_bar, 1u);
        unsigned target = old - (old % gridDim.x) + gridDim.x;
        while (*(volatile unsigned*)&g_bar < target) __nanosleep(64);
        __threadfence();
    }
    __syncthreads();
}

__global__ __launch_bounds__(THREADS, 1) void k1_fused(
    const float* __restrict__ x, const float* __restrict__ Wp, const float* __restrict__ bp,
    const float* __restrict__ We, const float* __restrict__ be,
    const float* __restrict__ Wo, const float* __restrict__ bo,
    float* __restrict__ out)
{
    extern __shared__ float sm[];
    float* WpT = sm + OFF_WPT;
    float* sS  = sm + OFF_S;
    float* bpS = sm + OFF_BP;
    float* csS = sm + OFF_CS;

    const int tid  = threadIdx.x;
    const int w    = tid >> 5, lane = tid & 31;
    float* xbuf = sm + OFF_XB + w * 1024;          // warp-private 4KB

    // ---- init: WpT transpose (padded rows), bp, cs ----
    for (int idx = tid; idx < F_DIM * C_DIM; idx += THREADS) {
        int k = idx >> 6, c = idx & 63;
        WpT[c * WPT_STRIDE + k] = Wp[idx];
    }
    if (tid < 64) { bpS[tid] = bp[tid]; csS[tid] = 0.f; }
    __syncthreads();

    // Phase A/B lane mapping: 2 nodes (of warp's 4) x 4 clusters
    const int cg = lane & 15, ng = lane >> 4;
    // Phase C lane mapping: 8 clusters x 8 features (of warp's 32-f slice)
    const int cg3 = lane & 7, fg = lane >> 3;
    const int c0C = cg3 * 8;

    ull Macc[4][8];                                // [c-pair][f]
    #pragma unroll
    for (int a = 0; a < 4; ++a)
        #pragma unroll
        for (int b = 0; b < 8; ++b) Macc[a][b] = 0ull;
    float csacc[4] = {0.f, 0.f, 0.f, 0.f};

    const int G = gridDim.x;

    for (int tile = blockIdx.x; tile < NTILES; tile += G) {
        const int node0 = tile * NT;
        const int nwbase = node0 + 4 * w;          // warp's first node

        // ===== Phase A: logits, k-parity packed accumulators (no CTA sync) =====
        ull accA[2][4];
        #pragma unroll
        for (int j = 0; j < 2; ++j)
            #pragma unroll
            for (int ci = 0; ci < 4; ++ci) accA[j][ci] = 0ull;

        #pragma unroll 1
        for (int ch = 0; ch < 4; ++ch) {
            __syncwarp();
            // stage warp's 4 nodes x 128 k (2KB), node-major rows of 512B
            #pragma unroll
            for (int r = 0; r < 4; ++r) {
                int node = nwbase + r;
                float4 v = make_float4(0.f, 0.f, 0.f, 0.f);
                if (node < N_NODES)
                    v = *(const float4*)(x + (size_t)node * F_DIM + ch * 128 + lane * 4);
                *(float4*)(xbuf + r * 128 + lane * 4) = v;
            }
            __syncwarp();

            const ulonglong2* xr0 = (const ulonglong2*)(xbuf + (ng * 2 + 0) * 128);
            const ulonglong2* xr1 = (const ulonglong2*)(xbuf + (ng * 2 + 1) * 128);
            const float* wbase = WpT + (cg * 4) * WPT_STRIDE + ch * 128;
            #pragma unroll 8
            for (int k4 = 0; k4 < 32; ++k4) {
                ulonglong2 x0 = xr0[k4];
                ulonglong2 x1 = xr1[k4];
                #pragma unroll
                for (int ci = 0; ci < 4; ++ci) {
                    ulonglong2 wv = *(const ulonglong2*)(wbase + ci * WPT_STRIDE + k4 * 4);
                    accA[0][ci] = fma2(wv.x, x0.x, accA[0][ci]);
                    accA[0][ci] = fma2(wv.y, x0.y, accA[0][ci]);
                    accA[1][ci] = fma2(wv.x, x1.x, accA[1][ci]);
                    accA[1][ci] = fma2(wv.y, x1.y, accA[1][ci]);
                }
            }
        }

        // ===== Phase B: warp-local softmax over 64 clusters (16-lane shfl) =====
        #pragma unroll
        for (int j = 0; j < 2; ++j) {
            const int nl = ng * 2 + j;             // 0..3 within warp
            const int node = nwbase + nl;
            float l[4];
            #pragma unroll
            for (int ci = 0; ci < 4; ++ci) {
                float lo, hi;
                unpack2(accA[j][ci], lo, hi);
                l[ci] = lo + hi + bpS[cg * 4 + ci];
            }
            float mx = fmaxf(fmaxf(l[0], l[1]), fmaxf(l[2], l[3]));
            #pragma unroll
            for (int d = 1; d < 16; d <<= 1) mx = fmaxf(mx, __shfl_xor_sync(0xffffffffu, mx, d));
            float e0 = __expf(l[0] - mx), e1 = __expf(l[1] - mx);
            float e2 = __expf(l[2] - mx), e3 = __expf(l[3] - mx);
            float s = e0 + e1 + e2 + e3;
            #pragma unroll
            for (int d = 1; d < 16; d <<= 1) s += __shfl_xor_sync(0xffffffffu, s, d);
            float r = __frcp_rn(s);
            if (node >= N_NODES) r = 0.f;
            float4 sv = make_float4(e0 * r, e1 * r, e2 * r, e3 * r);
            csacc[0] += sv.x; csacc[1] += sv.y; csacc[2] += sv.z; csacc[3] += sv.w;
            *(float4*)(sS + (4 * w + nl) * 64 + cg * 4) = sv;
        }
        __syncthreads();                           // publish s to all warps

        // ===== Phase C: M[c][f] += s[n][c] * x[n][f]  (warp-private staging) =====
        #pragma unroll 1
        for (int q = 0; q < 2; ++q) {
            __syncwarp();
            // stage 32 nodes x warp's 32-f slice (4KB)
            #pragma unroll
            for (int r = 0; r < 8; ++r) {
                int nl = q * 32 + r * 4 + fg;
                int node = node0 + nl;
                float4 v = make_float4(0.f, 0.f, 0.f, 0.f);
                if (node < N_NODES)
                    v = *(const float4*)(x + (size_t)node * F_DIM + 32 * w + cg3 * 4);
                *(float4*)(xbuf + (r * 4 + fg) * 32 + cg3 * 4) = v;
            }
            __syncwarp();

            #pragma unroll 4
            for (int n = 0; n < 32; ++n) {
                const int ns = q * 32 + n;
                ulonglong2 sA = *(const ulonglong2*)(sS + ns * 64 + c0C);
                ulonglong2 sB = *(const ulonglong2*)(sS + ns * 64 + c0C + 4);
                float4 xa = *(const float4*)(xbuf + n * 32 + fg * 8);
                float4 xb = *(const float4*)(xbuf + n * 32 + fg * 8 + 4);
                float xs[8] = { xa.x, xa.y, xa.z, xa.w, xb.x, xb.y, xb.z, xb.w };
                #pragma unroll
                for (int jj = 0; jj < 8; ++jj) {
                    ull p = pack2(xs[jj], xs[jj]);
                    Macc[0][jj] = fma2(sA.x, p, Macc[0][jj]);
                    Macc[1][jj] = fma2(sA.y, p, Macc[1][jj]);
                    Macc[2][jj] = fma2(sB.x, p, Macc[2][jj]);
                    Macc[3][jj] = fma2(sB.y, p, Macc[3][jj]);
                }
            }
        }
        __syncthreads();                           // retire s before next tile's B
    }

    // ---- per-block partial M ----
    {
        float* mp = g_Mpart + (size_t)blockIdx.x * (C_DIM * F_DIM);
        const int fb = 32 * w + fg * 8;
        #pragma unroll
        for (int cp = 0; cp < 4; ++cp)
            #pragma unroll
            for (int jj = 0; jj < 8; ++jj) {
                float lo, hi;
                unpack2(Macc[cp][jj], lo, hi);
                mp[(c0C + 2 * cp + 0) * F_DIM + fb + jj] = lo;
                mp[(c0C + 2 * cp + 1) * F_DIM + fb + jj] = hi;
            }
    }
    // ---- per-block partial colsum(s) ----
    #pragma unroll
    for (int ci = 0; ci < 4; ++ci) atomicAdd(&csS[cg * 4 + ci], csacc[ci]);
    __syncthreads();
    if (tid < 64) g_cspart[blockIdx.x * 64 + tid] = csS[tid];

    // ================= In-kernel epilogue (grid-synchronized) =================
    const int G2 = gridDim.x;
    grid_sync();

    {
        unsigned idx = blockIdx.x * (unsigned)THREADS + (unsigned)tid;
        if (idx < C_DIM * F_DIM) {
            float s = 0.f;
            #pragma unroll 4
            for (int b = 0; b < G2; ++b) s += g_Mpart[(size_t)b * (C_DIM * F_DIM) + idx];
            g_M[idx] = s;
        }
        if (blockIdx.x == 64 && tid < C_DIM) {
            float s = 0.f;
            #pragma unroll 4
            for (int b = 0; b < G2; ++b) s += g_cspart[b * C_DIM + tid];
            g_cs[tid] = s;
        }
    }

    grid_sync();

    // pooled = M @ We + cs (x) be : blocks 0..15, 4 clusters each, f = tid
    if (blockIdx.x < 16) {
        const int f = tid;
        const int cb = blockIdx.x * 4;
        const float bef = be[f];
        float a0 = g_cs[cb + 0] * bef;
        float a1 = g_cs[cb + 1] * bef;
        float a2 = g_cs[cb + 2] * bef;
        float a3 = g_cs[cb + 3] * bef;
        #pragma unroll 8
        for (int k = 0; k < F_DIM; ++k) {
            float wv = We[(size_t)k * F_DIM + f];
            a0 += g_M[(cb + 0) * F_DIM + k] * wv;
            a1 += g_M[(cb + 1) * F_DIM + k] * wv;
            a2 += g_M[(cb + 2) * F_DIM + k] * wv;
            a3 += g_M[(cb + 3) * F_DIM + k] * wv;
        }
        g_pooled[(cb + 0) * F_DIM + f] = a0;
        g_pooled[(cb + 1) * F_DIM + f] = a1;
        g_pooled[(cb + 2) * F_DIM + f] = a2;
        g_pooled[(cb + 3) * F_DIM + f] = a3;
    }

    grid_sync();

    // out = pooled @ Wo + bo : blocks 0..63 (one cluster each), k split 2 ways
    if (blockIdx.x < 64) {
        const int o = tid & 255, q = tid >> 8, c = blockIdx.x;
        float a = 0.f;
        const int kbeg = q * 256;
        #pragma unroll 8
        for (int k = kbeg; k < kbeg + 256; ++k)
            a += g_pooled[c * F_DIM + k] * Wo[(size_t)k * O_DIM + o];
        float* rsm = sm + OFF_XB;
        rsm[q * 256 + o] = a;
        __syncthreads();
        if (q == 0) out[c * O_DIM + o] = rsm[o] + rsm[256 + o] + bo[o];
    }
}

extern "C" void kernel_launch(void* const* d_in, const int* in_sizes, int n_in,
                              void* d_out, int out_size) {
    const float* x  = (const float*)d_in[0];
    // d_in[1] = edge_index (int64), d_in[2] = batch (int64): unused by the output
    const float* Wp = (const float*)d_in[3];
    const float* bp = (const float*)d_in[4];
    const float* We = (const float*)d_in[5];
    const float* be = (const float*)d_in[6];
    const float* Wo = (const float*)d_in[7];
    const float* bo = (const float*)d_in[8];
    float* out = (float*)d_out;

    int dev = 0;
    cudaGetDevice(&dev);
    int smc_n = GRID_MAX;
    cudaDeviceGetAttribute(&smc_n, cudaDevAttrMultiProcessorCount, dev);
    int G = smc_n < GRID_MAX ? smc_n : GRID_MAX;

    const int SMEM1 = SMEM_FLOATS * (int)sizeof(float);   // 214528 B
    cudaFuncSetAttribute(k1_fused, cudaFuncAttributeMaxDynamicSharedMemorySize, SMEM1);
    k1_fused<<<G, THREADS, SMEM1>>>(x, Wp, bp, We, be, Wo, bo, out);
}

// round 12
// speedup vs baseline: 2.1581x; 2.1581x over previous
#include <cuda_runtime.h>
#include <cuda_fp16.h>
#include <cstdint>

#define N_NODES 50000
#define F_DIM 512
#define C_DIM 64
#define O_DIM 256
#define GRID_MAX 152
#define NT 128
#define NTILES ((N_NODES + NT - 1) / NT)   // 391
#define THREADS 512

typedef unsigned long long ull;

// ---- smem byte offsets ----
#define OFF_WB   0          // W frags fp16: [2 seg][32 ks][8 ct][32 lane][8B] = 131072
#define OFF_XU   131072     // union 64KB: Phase A A-frag chunk / Phase C xs4
#define OFF_S    196608     // logits/s fp32 [128 n][16 float4] (c4 XOR n&15) = 32768
#define OFF_BP   229376     // 256B
#define SMEM_TOTAL 229664

// Scratch (static device arrays; no allocation)
__device__ float g_Mpart[GRID_MAX * C_DIM * F_DIM];
__device__ float g_cspart[GRID_MAX * C_DIM];
__device__ float g_M[C_DIM * F_DIM];
__device__ float g_cs[C_DIM];
__device__ float g_pooled[C_DIM * F_DIM];
__device__ unsigned g_bar;

static __device__ __forceinline__ ull pack2(float lo, float hi) {
    ull r; asm("mov.b64 %0, {%1,%2};" : "=l"(r) : "f"(lo), "f"(hi)); return r;
}
static __device__ __forceinline__ void unpack2(ull v, float& lo, float& hi) {
    asm("mov.b64 {%0,%1}, %2;" : "=f"(lo), "=f"(hi) : "l"(v));
}
static __device__ __forceinline__ ull fma2(ull a, ull b, ull c) {
    ull d; asm("fma.rn.f32x2 %0, %1, %2, %3;" : "=l"(d) : "l"(a), "l"(b), "l"(c)); return d;
}
static __device__ __forceinline__ void mma16816(float* d, const uint32_t* a, uint32_t b0, uint32_t b1) {
    asm volatile(
        "mma.sync.aligned.m16n8k16.row.col.f32.f16.f16.f32 "
        "{%0,%1,%2,%3}, {%4,%5,%6,%7}, {%8,%9}, {%0,%1,%2,%3};"
        : "+f"(d[0]), "+f"(d[1]), "+f"(d[2]), "+f"(d[3])
        : "r"(a[0]), "r"(a[1]), "r"(a[2]), "r"(a[3]), "r"(b0), "r"(b1));
}

// Grid-wide barrier: all CTAs resident (grid == #SMs, occ 1). Monotonic counter.
static __device__ __forceinline__ void grid_sync() {
    __syncthreads();
    __threadfence();
    if (threadIdx.x == 0) {
        unsigned old = atomicAdd(&g_bar, 1u);
        unsigned target = old - (old % gridDim.x) + gridDim.x;
        while (*(volatile unsigned*)&g_bar < target) __nanosleep(64);
        __threadfence();
    }
    __syncthreads();
}

__global__ __launch_bounds__(THREADS, 1) void k1_fused(
    const float* __restrict__ x, const float* __restrict__ Wp, const float* __restrict__ bp,
    const float* __restrict__ We, const float* __restrict__ be,
    const float* __restrict__ Wo, const float* __restrict__ bo,
    float* __restrict__ out)
{
    extern __shared__ char smc[];
    float4* xs4 = (float4*)(smc + OFF_XU);
    float4* ss4 = (float4*)(smc + OFF_S);
    float*  sSf = (float*)(smc + OFF_S);
    float*  bpS = (float*)(smc + OFF_BP);

    const int tid = threadIdx.x;
    const int G = gridDim.x;

    // ---- one-time init: Wp -> fp16 hi/lo B-fragment layout; bp stage ----
    // B-frag (m16n8k16 .col): lane = col*4 + (kpair&3), reg = kpair>>2, par = k&1.
    for (int idx = tid; idx < F_DIM * C_DIM; idx += THREADS) {
        int k = idx >> 6, c = idx & 63;
        float wv = Wp[idx];
        __half hh = __float2half_rn(wv);
        __half hl = __float2half_rn(wv - __half2float(hh));
        int ks = k >> 4, kk = k & 15, kp = kk >> 1, par = kk & 1;
        int ct = c >> 3, col = c & 7;
        int reg = kp >> 2, lane = col * 4 + (kp & 3);
        int off = (((ks) * 8 + ct) * 32 + lane) * 8 + reg * 4 + par * 2;
        *(__half*)(smc + OFF_WB + off) = hh;
        *(__half*)(smc + OFF_WB + 65536 + off) = hl;
    }
    if (tid < 64) bpS[tid] = bp[tid];
    __syncthreads();

    const int w = tid >> 5, lane = tid & 31;
    const int nt = w >> 1, chalf = w & 1;          // mma: warp = (n-tile, c-half)
    const int cq = tid & 15, ng = tid >> 4;        // softmax: 4 clusters x 4 nodes
    const int f4 = lane;                           // Phase C: R4 mapping (w = c-quad)

    ull Macc[4][4][2];
    #pragma unroll
    for (int a = 0; a < 4; ++a)
        #pragma unroll
        for (int b = 0; b < 4; ++b) { Macc[a][b][0] = 0ull; Macc[a][b][1] = 0ull; }
    float cs0 = 0.f, cs1 = 0.f, cs2 = 0.f, cs3 = 0.f;

    for (int tile = blockIdx.x; tile < NTILES; tile += G) {
        const int node0 = tile * NT;

        // ===== Phase A: logits = xh @ (Wh + Wl) via mma.sync, 2 k-chunks =====
        float accA[4][4];
        #pragma unroll
        for (int t = 0; t < 4; ++t)
            #pragma unroll
            for (int r = 0; r < 4; ++r) accA[t][r] = 0.f;

        #pragma unroll 1
        for (int cc = 0; cc < 2; ++cc) {
            __syncthreads();
            // stage A-frags: x[128n][256k] fp32 -> fp16, permuted to fragment order
            #pragma unroll
            for (int it = 0; it < 16; ++it) {
                int j = tid + it * THREADS;        // 0..8191
                int kq = j & 63, n = j >> 6;
                int node = node0 + n;
                float4 v = make_float4(0.f, 0.f, 0.f, 0.f);
                if (node < N_NODES)
                    v = *(const float4*)(x + (size_t)node * F_DIM + cc * 256 + kq * 4);
                uint32_t h01, h23;
                { __half2 t2 = __floats2half2_rn(v.x, v.y); h01 = *(uint32_t*)&t2; }
                { __half2 t2 = __floats2half2_rn(v.z, v.w); h23 = *(uint32_t*)&t2; }
                int ksl = kq >> 2, kqq = kq & 3;
                int ntn = n >> 4, rr = n & 15, rlow = rr & 7, rhi = rr >> 3;
                int p0 = kqq * 2;
                int lane0 = rlow * 4 + (p0 & 3);
                int lane1 = rlow * 4 + ((p0 + 1) & 3);
                int reg0 = ((p0 >> 2) << 1) | rhi;
                *(uint32_t*)(smc + OFF_XU + ((ksl * 8 + ntn) * 32 + lane0) * 16 + reg0 * 4) = h01;
                *(uint32_t*)(smc + OFF_XU + ((ksl * 8 + ntn) * 32 + lane1) * 16 + reg0 * 4) = h23;
            }
            __syncthreads();

            #pragma unroll 4
            for (int ks = 0; ks < 16; ++ks) {
                uint4 av = *(const uint4*)(smc + OFF_XU + ((ks * 8 + nt) * 32 + lane) * 16);
                const int ksg = cc * 16 + ks;
                #pragma unroll
                for (int seg = 0; seg < 2; ++seg) {
                    #pragma unroll
                    for (int t = 0; t < 4; ++t) {
                        int ct = chalf * 4 + t;
                        uint2 bv = *(const uint2*)(smc + OFF_WB + seg * 65536 +
                                                   ((ksg * 8 + ct) * 32 + lane) * 8);
                        mma16816(accA[t], (const uint32_t*)&av, bv.x, bv.y);
                    }
                }
            }
        }

        // write logits to sS: cell(n, c4) at n*16 + (c4 ^ (n&15)), 4 floats per cell
        __syncthreads();
        {
            const int r0 = nt * 16 + (lane >> 2);
            const int r1 = r0 + 8;
            #pragma unroll
            for (int t = 0; t < 4; ++t) {
                int c = chalf * 32 + t * 8 + (lane & 3) * 2;
                int c4 = c >> 2, ci = c & 3;
                float* p0 = sSf + r0 * 64 + (c4 ^ (r0 & 15)) * 4 + ci;
                float* p1 = sSf + r1 * 64 + (c4 ^ (r1 & 15)) * 4 + ci;
                p0[0] = accA[t][0]; p0[1] = accA[t][1];
                p1[0] = accA[t][2]; p1[1] = accA[t][3];
            }
        }
        __syncthreads();

        // ===== Phase B: softmax (thread = 4 clusters x 4 nodes, 16-lane shfl) =====
        #pragma unroll
        for (int i = 0; i < 4; ++i) {
            const int n = ng * 4 + i;
            float4 lv = ss4[n * 16 + (cq ^ (n & 15))];
            float l0 = lv.x + bpS[cq * 4 + 0];
            float l1 = lv.y + bpS[cq * 4 + 1];
            float l2 = lv.z + bpS[cq * 4 + 2];
            float l3 = lv.w + bpS[cq * 4 + 3];
            float m = fmaxf(fmaxf(l0, l1), fmaxf(l2, l3));
            #pragma unroll
            for (int d = 1; d < 16; d <<= 1) m = fmaxf(m, __shfl_xor_sync(0xffffffffu, m, d));
            float e0 = __expf(l0 - m), e1 = __expf(l1 - m), e2 = __expf(l2 - m), e3 = __expf(l3 - m);
            float s = e0 + e1 + e2 + e3;
            #pragma unroll
            for (int d = 1; d < 16; d <<= 1) s += __shfl_xor_sync(0xffffffffu, s, d);
            float r = __frcp_rn(s);
            if (node0 + n >= N_NODES) r = 0.f;
            float4 sv = make_float4(e0 * r, e1 * r, e2 * r, e3 * r);
            cs0 += sv.x; cs1 += sv.y; cs2 += sv.z; cs3 += sv.w;
            ss4[n * 16 + (cq ^ (n & 15))] = sv;
        }

        // ===== Phase C: M[c][f] += s[n][c] * x[n][f]  (R4 exact fp32 SIMT) =====
        #pragma unroll
        for (int kc = 0; kc < 4; ++kc) {
            __syncthreads();
            #pragma unroll
            for (int it = 0; it < 8; ++it) {
                int j = tid + it * THREADS;
                int k4 = j & 31, n = j >> 5;
                int node = node0 + n;
                float4 v = make_float4(0.f, 0.f, 0.f, 0.f);
                if (node < N_NODES) v = *(const float4*)(x + (size_t)node * F_DIM + kc * 128 + k4 * 4);
                xs4[k4 * 128 + (n ^ (k4 & 7))] = v;
            }
            __syncthreads();

            const ulonglong2* xcol = (const ulonglong2*)xs4 + f4 * 128;
            const int sw = f4 & 7;
            #pragma unroll 4
            for (int n = 0; n < NT; ++n) {
                float4 sv = ss4[n * 16 + (w ^ (n & 15))];   // warp-uniform broadcast
                ulonglong2 xv = xcol[n ^ sw];
                ull t0 = pack2(sv.x, sv.x), t1 = pack2(sv.y, sv.y);
                ull t2 = pack2(sv.z, sv.z), t3 = pack2(sv.w, sv.w);
                Macc[kc][0][0] = fma2(xv.x, t0, Macc[kc][0][0]);
                Macc[kc][0][1] = fma2(xv.y, t0, Macc[kc][0][1]);
                Macc[kc][1][0] = fma2(xv.x, t1, Macc[kc][1][0]);
                Macc[kc][1][1] = fma2(xv.y, t1, Macc[kc][1][1]);
                Macc[kc][2][0] = fma2(xv.x, t2, Macc[kc][2][0]);
                Macc[kc][2][1] = fma2(xv.y, t2, Macc[kc][2][1]);
                Macc[kc][3][0] = fma2(xv.x, t3, Macc[kc][3][0]);
                Macc[kc][3][1] = fma2(xv.y, t3, Macc[kc][3][1]);
            }
        }
        __syncthreads();   // s buffer reused as logits next tile
    }

    // ---- per-block partial M ----
    #pragma unroll
    for (int kc = 0; kc < 4; ++kc)
        #pragma unroll
        for (int cc = 0; cc < 4; ++cc) {
            float a, b, c2, d;
            unpack2(Macc[kc][cc][0], a, b);
            unpack2(Macc[kc][cc][1], c2, d);
            int c = w * 4 + cc;
            int f = kc * 128 + f4 * 4;
            *(float4*)(g_Mpart + (size_t)blockIdx.x * (C_DIM * F_DIM) + c * F_DIM + f) =
                make_float4(a, b, c2, d);
        }
    // ---- per-block partial colsum(s) ----
    // Scratch lives in the (now dead) s/logits region: strictly in-bounds.
    {
        float* csS = (float*)(smc + OFF_S);
        __syncthreads();                     // everyone done with ss4 reads
        if (tid < 64) csS[tid] = 0.f;
        __syncthreads();
        atomicAdd(&csS[cq * 4 + 0], cs0);
        atomicAdd(&csS[cq * 4 + 1], cs1);
        atomicAdd(&csS[cq * 4 + 2], cs2);
        atomicAdd(&csS[cq * 4 + 3], cs3);
        __syncthreads();
        if (tid < 64) g_cspart[blockIdx.x * 64 + tid] = csS[tid];
    }

    // ================= In-kernel epilogue (grid-synchronized) =================
    grid_sync();

    {
        unsigned idx = blockIdx.x * (unsigned)THREADS + (unsigned)tid;
        if (idx < C_DIM * F_DIM) {
            float s = 0.f;
            #pragma unroll 4
            for (int b = 0; b < G; ++b) s += g_Mpart[(size_t)b * (C_DIM * F_DIM) + idx];
            g_M[idx] = s;
        }
        if (blockIdx.x == 64 && tid < C_DIM) {
            float s = 0.f;
            #pragma unroll 4
            for (int b = 0; b < G; ++b) s += g_cspart[b * C_DIM + tid];
            g_cs[tid] = s;
        }
    }

    grid_sync();

    // pooled = M @ We + cs (x) be : blocks 0..15, 4 clusters each, f = tid
    if (blockIdx.x < 16) {
        const int f = tid;
        const int cb = blockIdx.x * 4;
        const float bef = be[f];
        float a0 = g_cs[cb + 0] * bef;
        float a1 = g_cs[cb + 1] * bef;
        float a2 = g_cs[cb + 2] * bef;
        float a3 = g_cs[cb + 3] * bef;
        #pragma unroll 8
        for (int k = 0; k < F_DIM; ++k) {
            float wv = We[(size_t)k * F_DIM + f];
            a0 += g_M[(cb + 0) * F_DIM + k] * wv;
            a1 += g_M[(cb + 1) * F_DIM + k] * wv;
            a2 += g_M[(cb + 2) * F_DIM + k] * wv;
            a3 += g_M[(cb + 3) * F_DIM + k] * wv;
        }
        g_pooled[(cb + 0) * F_DIM + f] = a0;
        g_pooled[(cb + 1) * F_DIM + f] = a1;
        g_pooled[(cb + 2) * F_DIM + f] = a2;
        g_pooled[(cb + 3) * F_DIM + f] = a3;
    }

    grid_sync();

    // out = pooled @ Wo + bo : blocks 0..63 (one cluster each), k split 2 ways
    if (blockIdx.x < 64) {
        const int o = tid & 255, q = tid >> 8, c = blockIdx.x;
        float a = 0.f;
        const int kbeg = q * 256;
        #pragma unroll 8
        for (int k = kbeg; k < kbeg + 256; ++k)
            a += g_pooled[c * F_DIM + k] * Wo[(size_t)k * O_DIM + o];
        float* rsm = (float*)(smc + OFF_XU);
        rsm[q * 256 + o] = a;
        __syncthreads();
        if (q == 0) out[c * O_DIM + o] = rsm[o] + rsm[256 + o] + bo[o];
    }
}

extern "C" void kernel_launch(void* const* d_in, const int* in_sizes, int n_in,
                              void* d_out, int out_size) {
    const float* x  = (const float*)d_in[0];
    // d_in[1] = edge_index (int64), d_in[2] = batch (int64): unused by the output
    const float* Wp = (const float*)d_in[3];
    const float* bp = (const float*)d_in[4];
    const float* We = (const float*)d_in[5];
    const float* be = (const float*)d_in[6];
    const float* Wo = (const float*)d_in[7];
    const float* bo = (const float*)d_in[8];
    float* out = (float*)d_out;

    int dev = 0;
    cudaGetDevice(&dev);
    int smc_n = GRID_MAX;
    cudaDeviceGetAttribute(&smc_n, cudaDevAttrMultiProcessorCount, dev);
    int G = smc_n < GRID_MAX ? smc_n : GRID_MAX;

    cudaFuncSetAttribute(k1_fused, cudaFuncAttributeMaxDynamicSharedMemorySize, SMEM_TOTAL);
    k1_fused<<<G, THREADS, SMEM_TOTAL>>>(x, Wp, bp, We, be, Wo, bo, out);
}